// round 8
// baseline (speedup 1.0000x reference)
#include <cuda_runtime.h>
#include <math.h>
#include <stdint.h>

#define NN 4096
#define CAPU 256

// ---------------- device globals (allocation-free scratch) ----------------
__device__ __align__(16) signed char g_B8[(size_t)NN * NN];   // B = m + m^T
__device__ __align__(16) signed char g_d8[NN];
__device__ int g_Dlist[NN];
__device__ int g_nD;
__device__ __align__(16) unsigned g_listT[(size_t)NN * CAPU]; // upper entries: idx | b<<16
__device__ int g_cntU[NN];
__device__ int g_rowsB[NN], g_rowsE[NN], g_rowsBB[NN], g_Bd[NN], g_colEf[NN];
__device__ unsigned long long g_triOrd, g_triAbs, g_c1, g_c2, g_c3;

__global__ void k_init() {
    int i = blockIdx.x * blockDim.x + threadIdx.x;
    if (i < NN) g_colEf[i] = 0;
    if (i == 0) {
        g_triOrd = 0ull; g_triAbs = 0ull;
        g_c1 = 0ull; g_c2 = 0ull; g_c3 = 0ull; g_nD = 0;
    }
}

// Fused: mod_adj + B = m + m^T + diag extraction. float4 path.
// hard = 1 <=> logit(p)+logit(u) > 0 <=> p + (u-1) > 0 (u-1 exact by Sterbenz).
__global__ void k_fuse(const float* __restrict__ ori, const float* __restrict__ cp,
                       const float* __restrict__ u, float* __restrict__ mod) {
    __shared__ unsigned m1w[32][9];
    __shared__ unsigned m2w[32][9];
    const int bx = blockIdx.x, by = blockIdx.y;
    if (bx < by) return;
    const int bi = by * 32, bj = bx * 32;
    const int tx = threadIdx.x;   // 0..7
    const int ty = threadIdx.y;   // 0..31
    const bool diag = (bx == by);

    {
        size_t idx = ((size_t)(bi + ty) * NN + bj + tx * 4) >> 2;
        float4 o = ((const float4*)ori)[idx];
        float4 c = ((const float4*)cp)[idx];
        float4 w = ((const float4*)u)[idx];
        float4 m;
        m.x = (c.x + (w.x - 1.0f) > 0.0f) ? -o.x : o.x;
        m.y = (c.y + (w.y - 1.0f) > 0.0f) ? -o.y : o.y;
        m.z = (c.z + (w.z - 1.0f) > 0.0f) ? -o.z : o.z;
        m.w = (c.w + (w.w - 1.0f) > 0.0f) ? -o.w : o.w;
        ((float4*)mod)[idx] = m;
        m1w[ty][tx] = ((unsigned)(int)m.x & 0xFFu)
                    | (((unsigned)(int)m.y & 0xFFu) << 8)
                    | (((unsigned)(int)m.z & 0xFFu) << 16)
                    | (((unsigned)(int)m.w & 0xFFu) << 24);
    }
    if (!diag) {
        size_t idx = ((size_t)(bj + ty) * NN + bi + tx * 4) >> 2;
        float4 o = ((const float4*)ori)[idx];
        float4 c = ((const float4*)cp)[idx];
        float4 w = ((const float4*)u)[idx];
        float4 m;
        m.x = (c.x + (w.x - 1.0f) > 0.0f) ? -o.x : o.x;
        m.y = (c.y + (w.y - 1.0f) > 0.0f) ? -o.y : o.y;
        m.z = (c.z + (w.z - 1.0f) > 0.0f) ? -o.z : o.z;
        m.w = (c.w + (w.w - 1.0f) > 0.0f) ? -o.w : o.w;
        ((float4*)mod)[idx] = m;
        m2w[ty][tx] = ((unsigned)(int)m.x & 0xFFu)
                    | (((unsigned)(int)m.y & 0xFFu) << 8)
                    | (((unsigned)(int)m.z & 0xFFu) << 16)
                    | (((unsigned)(int)m.w & 0xFFu) << 24);
    }
    __syncthreads();
    {   // B tile1: rows bi+ty, cols bj+tx*4..+3
        unsigned w1 = m1w[ty][tx];
        unsigned out = 0;
        #pragma unroll
        for (int q = 0; q < 4; q++) {
            int a = (int)(w1 << (24 - 8 * q)) >> 24;
            unsigned wt = diag ? m1w[tx * 4 + q][ty >> 2] : m2w[tx * 4 + q][ty >> 2];
            int b = (int)(wt << (24 - 8 * (ty & 3))) >> 24;
            out |= ((unsigned)(a + b) & 0xFFu) << (8 * q);
        }
        *(unsigned*)(g_B8 + (size_t)(bi + ty) * NN + bj + tx * 4) = out;
    }
    if (!diag) {  // B tile2: rows bj+ty, cols bi+tx*4..+3
        unsigned w1 = m2w[ty][tx];
        unsigned out = 0;
        #pragma unroll
        for (int q = 0; q < 4; q++) {
            int a = (int)(w1 << (24 - 8 * q)) >> 24;
            unsigned wt = m1w[tx * 4 + q][ty >> 2];
            int b = (int)(wt << (24 - 8 * (ty & 3))) >> 24;
            out |= ((unsigned)(a + b) & 0xFFu) << (8 * q);
        }
        *(unsigned*)(g_B8 + (size_t)(bj + ty) * NN + bi + tx * 4) = out;
    }
    if (diag && tx == (ty >> 2)) {
        int d = (int)(m1w[ty][tx] << (24 - 8 * (ty & 3))) >> 24;
        g_d8[bi + ty] = (signed char)d;
        if (d != 0) { int t = atomicAdd(&g_nD, 1); g_Dlist[t] = bi + ty; }
    }
}

// Per-row: upper lists (sorted), row sums (B, E, B^2, B*d), colEf atomics for rows in D.
__global__ void __launch_bounds__(256) k_lists() {
    __shared__ int wtot[8], woff[8];
    __shared__ int wsum[32];
    const int r = blockIdx.x, tid = threadIdx.x, lane = tid & 31, wid = tid >> 5;
    const int dr = (int)g_d8[r];
    uint4 bw4 = *(const uint4*)(g_B8 + (size_t)r * NN + tid * 16);
    uint4 dw4 = *(const uint4*)(g_d8 + tid * 16);
    unsigned bw[4] = {bw4.x, bw4.y, bw4.z, bw4.w};
    unsigned dw[4] = {dw4.x, dw4.y, dw4.z, dw4.w};

    int sB = 0, sBB = 0, sBd = 0, sE = 0, cnt = 0;
    unsigned nzm[4], gtm[4], ew[4];
    #pragma unroll
    for (int q = 0; q < 4; q++) {
        unsigned b = bw[q], d = dw[q];
        sB  = __dp4a((int)b, 0x01010101, sB);
        sBB = __dp4a((int)b, (int)b, sBB);
        sBd = __dp4a((int)b, (int)d, sBd);
        unsigned e;
        if (d == 0u) {
            e = (unsigned)__vabsss4((int)b);
        } else {
            e = 0;
            #pragma unroll
            for (int t = 0; t < 4; t++) {
                int bt = (int)(b << (24 - 8 * t)) >> 24;
                int dt = (int)(d << (24 - 8 * t)) >> 24;
                int et = dt ? (abs(bt - dt) - 1) : abs(bt);
                e |= ((unsigned)et & 0xFFu) << (8 * t);
            }
        }
        ew[q] = e;
        sE = __dp4a((int)e, 0x01010101, sE);
        nzm[q] = ~__vcmpeq4(b, 0u);
        int w0 = tid * 16 + q * 4;
        int rel = r - w0;
        gtm[q] = rel < 0 ? 0xFFFFFFFFu : (rel >= 3 ? 0u : (0xFFFFFFFFu << ((rel + 1) * 8)));
        cnt += __popc(nzm[q] & gtm[q]) >> 3;
    }
    // colEf: rows r in D add their E-row (E nonzero only where B nonzero)
    if (dr != 0) {
        #pragma unroll
        for (int q = 0; q < 4; q++) {
            unsigned mk = nzm[q];
            while (mk) {
                int bit = __ffs(mk) - 1;
                int t = bit >> 3;
                mk &= ~(0xFFu << (t * 8));
                int et = (int)(ew[q] << (24 - 8 * t)) >> 24;
                if (et) atomicAdd(&g_colEf[tid * 16 + q * 4 + t], et);
            }
        }
    }
    // block exclusive scan for sorted upper-list positions
    int inc = cnt;
    #pragma unroll
    for (int o = 1; o < 32; o <<= 1) {
        int v = __shfl_up_sync(0xFFFFFFFFu, inc, o);
        if (lane >= o) inc += v;
    }
    if (lane == 31) wtot[wid] = inc;
    __syncthreads();
    if (tid == 0) {
        int s = 0;
        #pragma unroll
        for (int w = 0; w < 8; w++) { woff[w] = s; s += wtot[w]; }
        g_cntU[r] = min(s, CAPU);
    }
    __syncthreads();
    int pos = woff[wid] + inc - cnt;
    #pragma unroll
    for (int q = 0; q < 4; q++) {
        unsigned mk = nzm[q] & gtm[q];
        while (mk) {
            int bit = __ffs(mk) - 1;
            int t = bit >> 3;
            mk &= ~(0xFFu << (t * 8));
            int bt = (int)(bw[q] << (24 - 8 * t)) >> 24;
            if (pos < CAPU)
                g_listT[(size_t)r * CAPU + pos] =
                    (unsigned)(tid * 16 + q * 4 + t) | (((unsigned)bt & 0xFFu) << 16);
            pos++;
        }
    }
    // row-sum reductions
    #pragma unroll
    for (int o = 16; o > 0; o >>= 1) {
        sB  += __shfl_down_sync(0xFFFFFFFFu, sB, o);
        sBB += __shfl_down_sync(0xFFFFFFFFu, sBB, o);
        sBd += __shfl_down_sync(0xFFFFFFFFu, sBd, o);
        sE  += __shfl_down_sync(0xFFFFFFFFu, sE, o);
    }
    if (lane == 0) { wsum[wid] = sB; wsum[8 + wid] = sBB; wsum[16 + wid] = sBd; wsum[24 + wid] = sE; }
    __syncthreads();
    if (tid == 0) {
        int a = 0, b = 0, c = 0, d = 0;
        #pragma unroll
        for (int w = 0; w < 8; w++) { a += wsum[w]; b += wsum[8 + w]; c += wsum[16 + w]; d += wsum[24 + w]; }
        g_rowsB[r] = a; g_rowsBB[r] = b; g_Bd[r] = c; g_rowsE[r] = d;
    }
}

// Ordered triangles j<k<i: accS += b_jk*b_ki*b_ij, accA += |...| (same product, abs).
__global__ void __launch_bounds__(256) k_tri() {
    __shared__ signed char s_b[NN];
    __shared__ unsigned s_l[CAPU];
    __shared__ long long redS[8], redA[8];
    const int j = blockIdx.x, tid = threadIdx.x, lane = tid & 31, wid = tid >> 5;
    ((int4*)s_b)[tid] = ((const int4*)(g_B8 + (size_t)j * NN))[tid];
    const int cU = g_cntU[j];
    for (int t = tid; t < cU; t += 256) s_l[t] = g_listT[(size_t)j * CAPU + t];
    __syncthreads();

    int accS = 0, accA = 0;
    for (int kk = wid; kk < cU; kk += 8) {
        unsigned e = s_l[kk];
        int k = (int)(e & 0xFFFFu);
        int bjk = (int)(e << 8) >> 24;
        int abjk = abs(bjk);
        const unsigned* lk = g_listT + (size_t)k * CAPU;
        int ck = __ldg(&g_cntU[k]);
        for (int t = lane; t < ck; t += 32) {
            unsigned e2 = __ldg(lk + t);
            int i = (int)(e2 & 0xFFFFu);
            int m = (((int)(e2 << 8)) >> 24) * (int)s_b[i];
            accS += bjk * m;
            accA += abjk * abs(m);
        }
    }
    #pragma unroll
    for (int o = 16; o > 0; o >>= 1) {
        accS += __shfl_down_sync(0xFFFFFFFFu, accS, o);
        accA += __shfl_down_sync(0xFFFFFFFFu, accA, o);
    }
    if (lane == 0) { redS[wid] = accS; redA[wid] = accA; }
    __syncthreads();
    if (tid == 0) {
        long long s = 0, a = 0;
        #pragma unroll
        for (int w = 0; w < 8; w++) { s += redS[w]; a += redA[w]; }
        atomicAdd(&g_triOrd, (unsigned long long)s);
        atomicAdd(&g_triAbs, (unsigned long long)a);
    }
}

// Per c in D: c1 += sum_{r: M[r,c]} (|B|^2)[c,r];  c2 += sum_{k in D: M[k,c]} sum_r M[r,k]|B[c,r]|
__global__ void __launch_bounds__(256) k_corr() {
    __shared__ int s_bw[1024];
    __shared__ short s_match[192];
    __shared__ int s_nm;
    const int bid = blockIdx.x;
    if (bid >= g_nD) return;
    const int c = g_Dlist[bid];
    const int dc = (int)g_d8[c];
    const int tid = threadIdx.x, lane = tid & 31, wid = tid >> 5;
    const int* src = (const int*)(g_B8 + (size_t)c * NN);
    #pragma unroll
    for (int w = tid; w < 1024; w += 256) s_bw[w] = src[w];
    if (tid == 0) s_nm = 0;
    __syncthreads();
    const signed char* s_bc = (const signed char*)s_bw;
    for (int r = tid; r < NN; r += 256) {
        int v = (int)s_bc[r];
        if (v != 0 && ((v > 0) == (dc > 0))) {
            int p = atomicAdd(&s_nm, 1);
            if (p < 192) s_match[p] = (short)r;
        }
    }
    __syncthreads();
    int nm = min(s_nm, 192);
    for (int mi = wid; mi < nm; mi += 8) {
        int r = (int)s_match[mi];
        const int* rw = (const int*)(g_B8 + (size_t)r * NN);
        int acc = 0;
        for (int w = lane; w < 1024; w += 32)
            acc = __dp4a((int)__vabsss4(__ldg(rw + w)), (int)__vabsss4(s_bw[w]), acc);
        #pragma unroll
        for (int o = 16; o > 0; o >>= 1) acc += __shfl_down_sync(0xFFFFFFFFu, acc, o);
        if (lane == 0) atomicAdd(&g_c1, (unsigned long long)(long long)acc);
    }
    const int nd = g_nD;
    for (int t = wid; t < nd; t += 8) {
        int k = g_Dlist[t];
        int vk = (int)s_bc[k];
        if (vk == 0 || ((vk > 0) != (dc > 0))) continue;
        int dk = (int)g_d8[k];
        const int* kw = (const int*)(g_B8 + (size_t)k * NN);
        int acc = 0;
        for (int w = lane; w < 1024; w += 32) {
            int bwv = __ldg(kw + w);
            unsigned mask = (dk > 0) ? __vcmpgts4(bwv, 0) : __vcmpgts4(0, bwv);
            acc = __dp4a((int)(mask & (unsigned)__vabsss4(s_bw[w])), 0x01010101, acc);
        }
        #pragma unroll
        for (int o = 16; o > 0; o >>= 1) acc += __shfl_down_sync(0xFFFFFFFFu, acc, o);
        if (lane == 0) atomicAdd(&g_c2, (unsigned long long)(long long)acc);
    }
}

// tr(M^3): all indices in D (<=96 assumed).
__global__ void k_m3() {
    __shared__ signed char Bs[96 * 96];
    __shared__ signed char sd[96];
    __shared__ int red[8];
    int nd = g_nD; if (nd > 96) nd = 96;
    const int tid = threadIdx.x, lane = tid & 31, wid = tid >> 5;
    for (int t = tid; t < nd; t += 256) sd[t] = g_d8[g_Dlist[t]];
    for (int t = tid; t < nd * nd; t += 256) {
        int a = t / nd, b = t - a * nd;
        Bs[t] = g_B8[(size_t)g_Dlist[a] * NN + g_Dlist[b]];
    }
    __syncthreads();
    int acc = 0;
    const int tot = nd * nd * nd;
    for (int t = tid; t < tot; t += 256) {
        int a = t / (nd * nd);
        int rem = t - a * nd * nd;
        int b = rem / nd, cc = rem - b * nd;
        int vab = Bs[a * nd + b], vbc = Bs[b * nd + cc], vca = Bs[cc * nd + a];
        bool m1 = vab && ((vab > 0) == (sd[b] > 0));
        bool m2 = vbc && ((vbc > 0) == (sd[cc] > 0));
        bool m3 = vca && ((vca > 0) == (sd[a] > 0));
        acc += (m1 && m2 && m3) ? 1 : 0;
    }
    #pragma unroll
    for (int o = 16; o > 0; o >>= 1) acc += __shfl_down_sync(0xFFFFFFFFu, acc, o);
    if (lane == 0) red[wid] = acc;
    __syncthreads();
    if (tid == 0) {
        int s = 0;
        #pragma unroll
        for (int w = 0; w < 8; w++) s += red[w];
        atomicAdd(&g_c3, (unsigned long long)(long long)s);
    }
}

__global__ void k_finish(float* __restrict__ out, int out_size) {
    __shared__ long long red[256];
    const int tid = threadIdx.x;
    long long T1 = 0, T2 = 0, S = 0, TA = 0, TB = 0, QS = 0, QA = 0;
    for (int i = tid; i < NN; i += 256) {
        int d = (int)g_d8[i];
        long long rb = g_rowsB[i];
        T1 += (long long)g_Bd[i] * rb;
        T2 += (long long)d * rb;
        S += d;
        TA += (long long)g_colEf[i] * (long long)g_rowsE[i];
        if (d != 0) {
            TB += g_rowsE[i];
            long long q = (long long)g_rowsBB[i] - 4;
            QS += (long long)d * q;
            QA += q;
        }
    }
    long long vals[7] = { T1, T2, S, TA, TB, QS, QA };
    #pragma unroll
    for (int q = 0; q < 7; q++) {
        red[tid] = vals[q];
        __syncthreads();
        for (int st = 128; st > 0; st >>= 1) {
            if (tid < st) red[tid] += red[tid + st];
            __syncthreads();
        }
        vals[q] = red[0];
        __syncthreads();
    }
    if (tid == 0) {
        long long triOrd = (long long)g_triOrd, triAbs = (long long)g_triAbs;
        long long c1 = (long long)g_c1, c2 = (long long)g_c2, c3 = (long long)g_c3;
        long long nD = g_nD;
        long long Sv = vals[2];
        long long trB3    = 6 * triOrd + 6 * vals[5] + 8 * Sv;
        long long trAbsB3 = 6 * triAbs + 6 * vals[6] + 8 * nD;
        long long trE3 = trAbsB3 - 6 * c1 + 12 * c2 - 8 * c3;
        long long tr3  = trB3 - 3 * vals[0] + 3 * Sv * vals[1] - Sv * Sv * Sv;
        long long tr3a = trE3 + 3 * vals[3] + 3 * nD * vals[4] + nD * nD * nD;
        out[out_size - 1] = (float)(0.5 * (1.0 + (double)tr3 / (double)tr3a));
    }
}

// ---------------- launch ----------------
extern "C" void kernel_launch(void* const* d_in, const int* in_sizes, int n_in,
                              void* d_out, int out_size) {
    const float* ori = (const float*)d_in[0];
    const float* cp  = (const float*)d_in[1];
    const float* u   = (const float*)d_in[2];
    float* out = (float*)d_out;

    k_init<<<16, 256>>>();
    k_fuse<<<dim3(128, 128), dim3(8, 32)>>>(ori, cp, u, out);
    k_lists<<<NN, 256>>>();
    k_corr<<<96, 256>>>();
    k_tri<<<NN, 256>>>();
    k_m3<<<1, 256>>>();
    k_finish<<<1, 256>>>(out, out_size);
}

// round 9
// speedup vs baseline: 1.3116x; 1.3116x over previous
#include <cuda_runtime.h>
#include <math.h>
#include <stdint.h>

#define NN 4096
#define CAP 512
#define CAPG (CAP / 2)

// ---------------- device globals (allocation-free scratch) ----------------
__device__ __align__(16) signed char g_B8[(size_t)NN * NN];   // B = m + m^T
__device__ __align__(16) signed char g_d8[NN];
__device__ int g_Dlist[NN];
__device__ int g_nD;
__device__ __align__(16) uint2 g_list2[(size_t)NN * CAPG];    // 2 entries per uint2
__device__ int g_cnt[NN];
__device__ int g_rowsB[NN], g_rowsE[NN], g_Bd[NN], g_colEf[NN];
__device__ unsigned long long g_triS, g_triE;

// Fused: mod_adj + B = m + m^T + diag + zeroing of accumulators.
// hard = 1 <=> logit(p)+logit(u) > 0 <=> p + (u-1) > 0 (u-1 exact by Sterbenz).
__global__ void k_fuse(const float* __restrict__ ori, const float* __restrict__ cp,
                       const float* __restrict__ u, float* __restrict__ mod) {
    __shared__ unsigned m1w[32][9];
    __shared__ unsigned m2w[32][9];
    const int bx = blockIdx.x, by = blockIdx.y;
    if (bx < by) return;
    const int bi = by * 32, bj = bx * 32;
    const int tx = threadIdx.x;   // 0..7
    const int ty = threadIdx.y;   // 0..31
    const int tid = ty * 8 + tx;
    const bool diag = (bx == by);

    if (diag && tid < 32) g_colEf[bi + tid] = 0;
    if (bx == 0 && by == 0 && tid == 0) { g_triS = 0ull; g_triE = 0ull; g_nD = 0; }

    {
        size_t idx = ((size_t)(bi + ty) * NN + bj + tx * 4) >> 2;
        float4 o = ((const float4*)ori)[idx];
        float4 c = ((const float4*)cp)[idx];
        float4 w = ((const float4*)u)[idx];
        float4 m;
        m.x = (c.x + (w.x - 1.0f) > 0.0f) ? -o.x : o.x;
        m.y = (c.y + (w.y - 1.0f) > 0.0f) ? -o.y : o.y;
        m.z = (c.z + (w.z - 1.0f) > 0.0f) ? -o.z : o.z;
        m.w = (c.w + (w.w - 1.0f) > 0.0f) ? -o.w : o.w;
        ((float4*)mod)[idx] = m;
        m1w[ty][tx] = ((unsigned)(int)m.x & 0xFFu)
                    | (((unsigned)(int)m.y & 0xFFu) << 8)
                    | (((unsigned)(int)m.z & 0xFFu) << 16)
                    | (((unsigned)(int)m.w & 0xFFu) << 24);
    }
    if (!diag) {
        size_t idx = ((size_t)(bj + ty) * NN + bi + tx * 4) >> 2;
        float4 o = ((const float4*)ori)[idx];
        float4 c = ((const float4*)cp)[idx];
        float4 w = ((const float4*)u)[idx];
        float4 m;
        m.x = (c.x + (w.x - 1.0f) > 0.0f) ? -o.x : o.x;
        m.y = (c.y + (w.y - 1.0f) > 0.0f) ? -o.y : o.y;
        m.z = (c.z + (w.z - 1.0f) > 0.0f) ? -o.z : o.z;
        m.w = (c.w + (w.w - 1.0f) > 0.0f) ? -o.w : o.w;
        ((float4*)mod)[idx] = m;
        m2w[ty][tx] = ((unsigned)(int)m.x & 0xFFu)
                    | (((unsigned)(int)m.y & 0xFFu) << 8)
                    | (((unsigned)(int)m.z & 0xFFu) << 16)
                    | (((unsigned)(int)m.w & 0xFFu) << 24);
    }
    __syncthreads();
    {   // B tile1: rows bi+ty, cols bj+tx*4..+3
        unsigned w1 = m1w[ty][tx];
        unsigned out = 0;
        #pragma unroll
        for (int q = 0; q < 4; q++) {
            int a = (int)(w1 << (24 - 8 * q)) >> 24;
            unsigned wt = diag ? m1w[tx * 4 + q][ty >> 2] : m2w[tx * 4 + q][ty >> 2];
            int b = (int)(wt << (24 - 8 * (ty & 3))) >> 24;
            out |= ((unsigned)(a + b) & 0xFFu) << (8 * q);
        }
        *(unsigned*)(g_B8 + (size_t)(bi + ty) * NN + bj + tx * 4) = out;
    }
    if (!diag) {  // B tile2: rows bj+ty, cols bi+tx*4..+3
        unsigned w1 = m2w[ty][tx];
        unsigned out = 0;
        #pragma unroll
        for (int q = 0; q < 4; q++) {
            int a = (int)(w1 << (24 - 8 * q)) >> 24;
            unsigned wt = m1w[tx * 4 + q][ty >> 2];
            int b = (int)(wt << (24 - 8 * (ty & 3))) >> 24;
            out |= ((unsigned)(a + b) & 0xFFu) << (8 * q);
        }
        *(unsigned*)(g_B8 + (size_t)(bj + ty) * NN + bi + tx * 4) = out;
    }
    if (diag && tx == (ty >> 2)) {
        int d = (int)(m1w[ty][tx] << (24 - 8 * (ty & 3))) >> 24;
        g_d8[bi + ty] = (signed char)d;
    }
}

// Per-row: full nnz lists (packed 2/uint2), row sums (B, E, B*d), colEf atomics, Dlist.
// List entry (row r, col c): idx=c, b=B[r,c], e=E[c,r] (with d_r).
__global__ void __launch_bounds__(256) k_lists() {
    __shared__ unsigned s_ent[CAP];
    __shared__ int scnt;
    __shared__ int wsum[24];
    const int r = blockIdx.x, tid = threadIdx.x, lane = tid & 31, wid = tid >> 5;
    if (tid == 0) scnt = 0;
    __syncthreads();
    const int dr = (int)g_d8[r];
    if (tid == 0 && dr != 0) { int t = atomicAdd(&g_nD, 1); g_Dlist[t] = r; }

    uint4 bw4 = *(const uint4*)(g_B8 + (size_t)r * NN + tid * 16);
    uint4 dw4 = *(const uint4*)(g_d8 + tid * 16);
    unsigned bw[4] = {bw4.x, bw4.y, bw4.z, bw4.w};
    unsigned dw[4] = {dw4.x, dw4.y, dw4.z, dw4.w};

    int sB = 0, sBd = 0, sE = 0, nzc = 0;
    unsigned nzm[4], ew[4];
    #pragma unroll
    for (int q = 0; q < 4; q++) {
        unsigned b = bw[q], d = dw[q];
        sB  = __dp4a((int)b, 0x01010101, sB);
        sBd = __dp4a((int)b, (int)d, sBd);
        unsigned e;
        if (d == 0u) {
            e = (unsigned)__vabsss4((int)b);
        } else {
            e = 0;
            #pragma unroll
            for (int t = 0; t < 4; t++) {
                int bt = (int)(b << (24 - 8 * t)) >> 24;
                int dt = (int)(d << (24 - 8 * t)) >> 24;
                int et = dt ? (abs(bt - dt) - 1) : abs(bt);
                e |= ((unsigned)et & 0xFFu) << (8 * t);
            }
        }
        ew[q] = e;
        sE = __dp4a((int)e, 0x01010101, sE);
        nzm[q] = ~__vcmpeq4(b, 0u);
        nzc += __popc(nzm[q]) >> 3;
    }
    // colEf: rows r in D add E[r,c] (E-support subset of B-support)
    if (dr != 0) {
        #pragma unroll
        for (int q = 0; q < 4; q++) {
            unsigned mk = nzm[q];
            while (mk) {
                int bit = __ffs(mk) - 1;
                int t = bit >> 3;
                mk &= ~(0xFFu << (t * 8));
                int et = (int)(ew[q] << (24 - 8 * t)) >> 24;
                if (et) atomicAdd(&g_colEf[tid * 16 + q * 4 + t], et);
            }
        }
    }
    // extraction into staging (order-free)
    int pos = 0;
    if (nzc) pos = atomicAdd(&scnt, nzc);
    #pragma unroll
    for (int q = 0; q < 4; q++) {
        unsigned mk = nzm[q];
        while (mk) {
            int bit = __ffs(mk) - 1;
            int t = bit >> 3;
            mk &= ~(0xFFu << (t * 8));
            int bt = (int)(bw[q] << (24 - 8 * t)) >> 24;
            int ec = dr ? (abs(bt - dr) - 1) : abs(bt);
            if (pos < CAP)
                s_ent[pos] = (unsigned)(tid * 16 + q * 4 + t)
                           | (((unsigned)bt & 0xFFu) << 16)
                           | (((unsigned)ec & 0xFFu) << 24);
            pos++;
        }
    }
    // row-sum reductions
    #pragma unroll
    for (int o = 16; o > 0; o >>= 1) {
        sB  += __shfl_down_sync(0xFFFFFFFFu, sB, o);
        sBd += __shfl_down_sync(0xFFFFFFFFu, sBd, o);
        sE  += __shfl_down_sync(0xFFFFFFFFu, sE, o);
    }
    if (lane == 0) { wsum[wid] = sB; wsum[8 + wid] = sBd; wsum[16 + wid] = sE; }
    __syncthreads();
    if (tid == 0) {
        int a = 0, c = 0, d = 0;
        #pragma unroll
        for (int w = 0; w < 8; w++) { a += wsum[w]; c += wsum[8 + w]; d += wsum[16 + w]; }
        g_rowsB[r] = a; g_Bd[r] = c; g_rowsE[r] = d;
    }
    int cnt = min(scnt, CAP);
    if (tid == 0) g_cnt[r] = cnt;
    int cnt4 = (cnt + 3) & ~3;
    for (int t = cnt + tid; t < cnt4; t += 256) s_ent[t] = 0;
    __syncthreads();
    int ng = cnt4 >> 1;
    for (int g = tid; g < ng; g += 256) {
        unsigned e0 = s_ent[2 * g], e1 = s_ent[2 * g + 1];
        unsigned x = (e0 & 0xFFFFu) | ((e1 & 0xFFFFu) << 16);
        unsigned y = __byte_perm(e0 >> 16, e1 >> 16, 0x5410);
        g_list2[(size_t)r * CAPG + g] = make_uint2(x, y);
    }
}

// Sparse traces: triS = tr(B^3), triE = tr(E^3) (complete — E_ii=0, supp(E) in supp(B)).
__global__ void __launch_bounds__(256) k_tri() {
    __shared__ uchar2 s_be[NN];      // (B[j,i], E[j,i]) — 8 KB, computed on the fly
    __shared__ uint2 jl[CAPG];
    __shared__ long long redS[8], redE[8];
    const int j = blockIdx.x, tid = threadIdx.x, lane = tid & 31, wid = tid >> 5;

    {   // build s_be from B row j + d vector
        uint4 b4 = *(const uint4*)(g_B8 + (size_t)j * NN + tid * 16);
        uint4 d4 = *(const uint4*)(g_d8 + tid * 16);
        unsigned bw[4] = {b4.x, b4.y, b4.z, b4.w};
        unsigned dw[4] = {d4.x, d4.y, d4.z, d4.w};
        unsigned wo[8];
        #pragma unroll
        for (int q = 0; q < 4; q++) {
            unsigned b = bw[q], d = dw[q];
            unsigned e;
            if (d == 0u) {
                e = (unsigned)__vabsss4((int)b);
            } else {
                e = 0;
                #pragma unroll
                for (int t = 0; t < 4; t++) {
                    int bt = (int)(b << (24 - 8 * t)) >> 24;
                    int dt = (int)(d << (24 - 8 * t)) >> 24;
                    int et = dt ? (abs(bt - dt) - 1) : abs(bt);
                    e |= ((unsigned)et & 0xFFu) << (8 * t);
                }
            }
            wo[2 * q]     = __byte_perm(b, e, 0x5140);   // (b0,e0,b1,e1)
            wo[2 * q + 1] = __byte_perm(b, e, 0x7362);   // (b2,e2,b3,e3)
        }
        int4* dst = (int4*)((char*)s_be + tid * 32);
        dst[0] = make_int4((int)wo[0], (int)wo[1], (int)wo[2], (int)wo[3]);
        dst[1] = make_int4((int)wo[4], (int)wo[5], (int)wo[6], (int)wo[7]);
    }
    const int cj = g_cnt[j];
    const int njg = ((cj + 3) & ~3) >> 1;
    for (int t = tid; t < njg; t += 256) jl[t] = g_list2[(size_t)j * CAPG + t];
    __syncthreads();

    int aS = 0, aE = 0;
    for (int kk = wid; kk < cj; kk += 8) {
        uint2 w = jl[kk >> 1];
        int hi = kk & 1;
        int k = hi ? (int)(w.x >> 16) : (int)(w.x & 0xFFFFu);
        int bkj = hi ? ((int)(w.y << 8) >> 24) : ((int)(w.y << 24) >> 24);
        int ekj = hi ? ((int)w.y >> 24)        : ((int)(w.y << 16) >> 24);
        const uint4* lk = (const uint4*)(g_list2 + (size_t)k * CAPG);
        int ck4 = (__ldg(&g_cnt[k]) + 3) >> 2;
        int sk = 0, ek = 0;
        for (int t = lane; t < ck4; t += 32) {
            uint4 w4 = __ldg(&lk[t]);
            {
                int i0 = (int)(w4.x & 0xFFFFu), i1 = (int)(w4.x >> 16);
                unsigned v0 = *(const unsigned short*)&s_be[i0];
                unsigned v1 = *(const unsigned short*)&s_be[i1];
                unsigned be2 = __byte_perm(v0, v1, 0x5410);
                sk = __dp4a((int)(w4.y & 0x00FF00FFu), (int)be2, sk);
                ek = __dp4a((int)(w4.y & 0xFF00FF00u), (int)be2, ek);
            }
            {
                int i0 = (int)(w4.z & 0xFFFFu), i1 = (int)(w4.z >> 16);
                unsigned v0 = *(const unsigned short*)&s_be[i0];
                unsigned v1 = *(const unsigned short*)&s_be[i1];
                unsigned be2 = __byte_perm(v0, v1, 0x5410);
                sk = __dp4a((int)(w4.w & 0x00FF00FFu), (int)be2, sk);
                ek = __dp4a((int)(w4.w & 0xFF00FF00u), (int)be2, ek);
            }
        }
        aS += bkj * sk;
        aE += ekj * ek;
    }
    #pragma unroll
    for (int o = 16; o > 0; o >>= 1) {
        aS += __shfl_down_sync(0xFFFFFFFFu, aS, o);
        aE += __shfl_down_sync(0xFFFFFFFFu, aE, o);
    }
    if (lane == 0) { redS[wid] = aS; redE[wid] = aE; }
    __syncthreads();
    if (tid == 0) {
        long long s = 0, t = 0;
        #pragma unroll
        for (int w = 0; w < 8; w++) { s += redS[w]; t += redE[w]; }
        atomicAdd(&g_triS, (unsigned long long)s);
        atomicAdd(&g_triE, (unsigned long long)t);
    }
}

// tr(A^3)  = tr(B^3) - 3*(Bd).(B1) + 3*(sum d)*(d.(B1)) - (sum d)^3
// tr(|A|^3)= tr(E^3) + 3*(E^T f).(E1) + 3*|D|*(f.(E1)) + |D|^3
__global__ void k_finish(float* __restrict__ out, int out_size) {
    __shared__ long long red[256];
    const int tid = threadIdx.x;
    long long T1 = 0, T2 = 0, S = 0, TA = 0, TB = 0;
    for (int i = tid; i < NN; i += 256) {
        int d = (int)g_d8[i];
        long long rb = g_rowsB[i];
        T1 += (long long)g_Bd[i] * rb;
        T2 += (long long)d * rb;
        S += d;
        TA += (long long)g_colEf[i] * (long long)g_rowsE[i];
        if (d != 0) TB += g_rowsE[i];
    }
    long long vals[5] = { T1, T2, S, TA, TB };
    #pragma unroll
    for (int q = 0; q < 5; q++) {
        red[tid] = vals[q];
        __syncthreads();
        for (int st = 128; st > 0; st >>= 1) {
            if (tid < st) red[tid] += red[tid + st];
            __syncthreads();
        }
        vals[q] = red[0];
        __syncthreads();
    }
    if (tid == 0) {
        long long triS = (long long)g_triS, triE = (long long)g_triE;
        long long nD = g_nD;
        long long Sv = vals[2];
        long long tr3  = triS - 3 * vals[0] + 3 * Sv * vals[1] - Sv * Sv * Sv;
        long long tr3a = triE + 3 * vals[3] + 3 * nD * vals[4] + nD * nD * nD;
        out[out_size - 1] = (float)(0.5 * (1.0 + (double)tr3 / (double)tr3a));
    }
}

// ---------------- launch ----------------
extern "C" void kernel_launch(void* const* d_in, const int* in_sizes, int n_in,
                              void* d_out, int out_size) {
    const float* ori = (const float*)d_in[0];
    const float* cp  = (const float*)d_in[1];
    const float* u   = (const float*)d_in[2];
    float* out = (float*)d_out;

    k_fuse<<<dim3(128, 128), dim3(8, 32)>>>(ori, cp, u, out);
    k_lists<<<NN, 256>>>();
    k_tri<<<NN, 256>>>();
    k_finish<<<1, 256>>>(out, out_size);
}

// round 10
// speedup vs baseline: 1.4531x; 1.1079x over previous
#include <cuda_runtime.h>
#include <math.h>
#include <stdint.h>

#define NN 4096
#define CAP 512
#define CAPG (CAP / 2)

// ---------------- device globals (allocation-free scratch) ----------------
__device__ __align__(16) signed char g_B8[(size_t)NN * NN];   // B = m + m^T
__device__ __align__(16) signed char g_d8[NN];
__device__ int g_nD;
__device__ __align__(16) uint2 g_list2[(size_t)NN * CAPG];    // 2 entries per uint2
__device__ int g_cnt[NN];
__device__ int g_rowsE[NN], g_colEf[NN];
__device__ unsigned long long g_triS, g_triE;
__device__ unsigned long long g_T1, g_T2, g_S, g_TA, g_TB;

// Fused: mod_adj + B = m + m^T + diag + zeroing of accumulators.
// hard = 1 <=> logit(p)+logit(u) > 0 <=> p + (u-1) > 0 (u-1 exact by Sterbenz).
__global__ void k_fuse(const float* __restrict__ ori, const float* __restrict__ cp,
                       const float* __restrict__ u, float* __restrict__ mod) {
    __shared__ unsigned m1w[32][9];
    __shared__ unsigned m2w[32][9];
    const int bx = blockIdx.x, by = blockIdx.y;
    if (bx < by) return;
    const int bi = by * 32, bj = bx * 32;
    const int tx = threadIdx.x;   // 0..7
    const int ty = threadIdx.y;   // 0..31
    const int tid = ty * 8 + tx;
    const bool diag = (bx == by);

    if (diag && tid < 32) g_colEf[bi + tid] = 0;
    if (bx == 0 && by == 0 && tid == 0) {
        g_triS = 0ull; g_triE = 0ull; g_nD = 0;
        g_T1 = 0ull; g_T2 = 0ull; g_S = 0ull; g_TA = 0ull; g_TB = 0ull;
    }

    {
        size_t idx = ((size_t)(bi + ty) * NN + bj + tx * 4) >> 2;
        float4 o = ((const float4*)ori)[idx];
        float4 c = ((const float4*)cp)[idx];
        float4 w = ((const float4*)u)[idx];
        float4 m;
        m.x = (c.x + (w.x - 1.0f) > 0.0f) ? -o.x : o.x;
        m.y = (c.y + (w.y - 1.0f) > 0.0f) ? -o.y : o.y;
        m.z = (c.z + (w.z - 1.0f) > 0.0f) ? -o.z : o.z;
        m.w = (c.w + (w.w - 1.0f) > 0.0f) ? -o.w : o.w;
        ((float4*)mod)[idx] = m;
        m1w[ty][tx] = ((unsigned)(int)m.x & 0xFFu)
                    | (((unsigned)(int)m.y & 0xFFu) << 8)
                    | (((unsigned)(int)m.z & 0xFFu) << 16)
                    | (((unsigned)(int)m.w & 0xFFu) << 24);
    }
    if (!diag) {
        size_t idx = ((size_t)(bj + ty) * NN + bi + tx * 4) >> 2;
        float4 o = ((const float4*)ori)[idx];
        float4 c = ((const float4*)cp)[idx];
        float4 w = ((const float4*)u)[idx];
        float4 m;
        m.x = (c.x + (w.x - 1.0f) > 0.0f) ? -o.x : o.x;
        m.y = (c.y + (w.y - 1.0f) > 0.0f) ? -o.y : o.y;
        m.z = (c.z + (w.z - 1.0f) > 0.0f) ? -o.z : o.z;
        m.w = (c.w + (w.w - 1.0f) > 0.0f) ? -o.w : o.w;
        ((float4*)mod)[idx] = m;
        m2w[ty][tx] = ((unsigned)(int)m.x & 0xFFu)
                    | (((unsigned)(int)m.y & 0xFFu) << 8)
                    | (((unsigned)(int)m.z & 0xFFu) << 16)
                    | (((unsigned)(int)m.w & 0xFFu) << 24);
    }
    __syncthreads();
    {   // B tile1: rows bi+ty, cols bj+tx*4..+3
        unsigned w1 = m1w[ty][tx];
        unsigned out = 0;
        #pragma unroll
        for (int q = 0; q < 4; q++) {
            int a = (int)(w1 << (24 - 8 * q)) >> 24;
            unsigned wt = diag ? m1w[tx * 4 + q][ty >> 2] : m2w[tx * 4 + q][ty >> 2];
            int b = (int)(wt << (24 - 8 * (ty & 3))) >> 24;
            out |= ((unsigned)(a + b) & 0xFFu) << (8 * q);
        }
        *(unsigned*)(g_B8 + (size_t)(bi + ty) * NN + bj + tx * 4) = out;
    }
    if (!diag) {  // B tile2: rows bj+ty, cols bi+tx*4..+3
        unsigned w1 = m2w[ty][tx];
        unsigned out = 0;
        #pragma unroll
        for (int q = 0; q < 4; q++) {
            int a = (int)(w1 << (24 - 8 * q)) >> 24;
            unsigned wt = m1w[tx * 4 + q][ty >> 2];
            int b = (int)(wt << (24 - 8 * (ty & 3))) >> 24;
            out |= ((unsigned)(a + b) & 0xFFu) << (8 * q);
        }
        *(unsigned*)(g_B8 + (size_t)(bj + ty) * NN + bi + tx * 4) = out;
    }
    if (diag && tx == (ty >> 2)) {
        int d = (int)(m1w[ty][tx] << (24 - 8 * (ty & 3))) >> 24;
        g_d8[bi + ty] = (signed char)d;
    }
}

// Per-row: full nnz lists (packed 2/uint2), row sums, colEf atomics, scalar-term atomics.
// List entry (row r, col c): idx=c, b=B[r,c], e=E[c,r] (with d_r).
__global__ void __launch_bounds__(256) k_lists() {
    __shared__ unsigned s_ent[CAP];
    __shared__ int scnt;
    __shared__ int wsum[24];
    const int r = blockIdx.x, tid = threadIdx.x, lane = tid & 31, wid = tid >> 5;
    if (tid == 0) scnt = 0;
    __syncthreads();
    const int dr = (int)g_d8[r];

    uint4 bw4 = *(const uint4*)(g_B8 + (size_t)r * NN + tid * 16);
    uint4 dw4 = *(const uint4*)(g_d8 + tid * 16);
    unsigned bw[4] = {bw4.x, bw4.y, bw4.z, bw4.w};
    unsigned dw[4] = {dw4.x, dw4.y, dw4.z, dw4.w};

    int sB = 0, sBd = 0, sE = 0, nzc = 0;
    unsigned nzm[4], ew[4];
    #pragma unroll
    for (int q = 0; q < 4; q++) {
        unsigned b = bw[q], d = dw[q];
        sB  = __dp4a((int)b, 0x01010101, sB);
        sBd = __dp4a((int)b, (int)d, sBd);
        unsigned e;
        if (d == 0u) {
            e = (unsigned)__vabsss4((int)b);
        } else {
            e = 0;
            #pragma unroll
            for (int t = 0; t < 4; t++) {
                int bt = (int)(b << (24 - 8 * t)) >> 24;
                int dt = (int)(d << (24 - 8 * t)) >> 24;
                int et = dt ? (abs(bt - dt) - 1) : abs(bt);
                e |= ((unsigned)et & 0xFFu) << (8 * t);
            }
        }
        ew[q] = e;
        sE = __dp4a((int)e, 0x01010101, sE);
        nzm[q] = ~__vcmpeq4(b, 0u);
        nzc += __popc(nzm[q]) >> 3;
    }
    // colEf: rows r in D add E[r,c] (E-support subset of B-support)
    if (dr != 0) {
        #pragma unroll
        for (int q = 0; q < 4; q++) {
            unsigned mk = nzm[q];
            while (mk) {
                int bit = __ffs(mk) - 1;
                int t = bit >> 3;
                mk &= ~(0xFFu << (t * 8));
                int et = (int)(ew[q] << (24 - 8 * t)) >> 24;
                if (et) atomicAdd(&g_colEf[tid * 16 + q * 4 + t], et);
            }
        }
    }
    // extraction into staging (order-free)
    int pos = 0;
    if (nzc) pos = atomicAdd(&scnt, nzc);
    #pragma unroll
    for (int q = 0; q < 4; q++) {
        unsigned mk = nzm[q];
        while (mk) {
            int bit = __ffs(mk) - 1;
            int t = bit >> 3;
            mk &= ~(0xFFu << (t * 8));
            int bt = (int)(bw[q] << (24 - 8 * t)) >> 24;
            int ec = dr ? (abs(bt - dr) - 1) : abs(bt);
            if (pos < CAP)
                s_ent[pos] = (unsigned)(tid * 16 + q * 4 + t)
                           | (((unsigned)bt & 0xFFu) << 16)
                           | (((unsigned)ec & 0xFFu) << 24);
            pos++;
        }
    }
    // row-sum reductions
    #pragma unroll
    for (int o = 16; o > 0; o >>= 1) {
        sB  += __shfl_down_sync(0xFFFFFFFFu, sB, o);
        sBd += __shfl_down_sync(0xFFFFFFFFu, sBd, o);
        sE  += __shfl_down_sync(0xFFFFFFFFu, sE, o);
    }
    if (lane == 0) { wsum[wid] = sB; wsum[8 + wid] = sBd; wsum[16 + wid] = sE; }
    __syncthreads();
    if (tid == 0) {
        int a = 0, c = 0, d = 0;
        #pragma unroll
        for (int w = 0; w < 8; w++) { a += wsum[w]; c += wsum[8 + w]; d += wsum[16 + w]; }
        g_rowsE[r] = d;
        // fold scalar reduction terms (order-free modular int64 atomics)
        atomicAdd(&g_T1, (unsigned long long)((long long)c * (long long)a));
        if (dr != 0) {
            atomicAdd(&g_T2, (unsigned long long)((long long)dr * (long long)a));
            atomicAdd(&g_S, (unsigned long long)(long long)dr);
            atomicAdd(&g_TB, (unsigned long long)(long long)d);
            atomicAdd(&g_nD, 1);
        }
    }
    int cnt = min(scnt, CAP);
    if (tid == 0) g_cnt[r] = cnt;
    int cnt4 = (cnt + 3) & ~3;
    for (int t = cnt + tid; t < cnt4; t += 256) s_ent[t] = 0;
    __syncthreads();
    int ng = cnt4 >> 1;
    for (int g = tid; g < ng; g += 256) {
        unsigned e0 = s_ent[2 * g], e1 = s_ent[2 * g + 1];
        unsigned x = (e0 & 0xFFFFu) | ((e1 & 0xFFFFu) << 16);
        unsigned y = __byte_perm(e0 >> 16, e1 >> 16, 0x5410);
        g_list2[(size_t)r * CAPG + g] = make_uint2(x, y);
    }
}

// Sparse traces: triS = tr(B^3), triE = tr(E^3); also folds TA = colEf.rowsE.
__global__ void __launch_bounds__(256) k_tri() {
    __shared__ uchar2 s_be[NN];      // (B[j,i], E[j,i]) — 8 KB, computed on the fly
    __shared__ uint2 jl[CAPG];
    __shared__ long long redS[8], redE[8];
    const int j = blockIdx.x, tid = threadIdx.x, lane = tid & 31, wid = tid >> 5;

    if (tid == 32) {  // TA term for this row (colEf complete after k_lists)
        atomicAdd(&g_TA, (unsigned long long)((long long)g_colEf[j] * (long long)g_rowsE[j]));
    }
    {   // build s_be from B row j + d vector
        uint4 b4 = *(const uint4*)(g_B8 + (size_t)j * NN + tid * 16);
        uint4 d4 = *(const uint4*)(g_d8 + tid * 16);
        unsigned bw[4] = {b4.x, b4.y, b4.z, b4.w};
        unsigned dw[4] = {d4.x, d4.y, d4.z, d4.w};
        unsigned wo[8];
        #pragma unroll
        for (int q = 0; q < 4; q++) {
            unsigned b = bw[q], d = dw[q];
            unsigned e;
            if (d == 0u) {
                e = (unsigned)__vabsss4((int)b);
            } else {
                e = 0;
                #pragma unroll
                for (int t = 0; t < 4; t++) {
                    int bt = (int)(b << (24 - 8 * t)) >> 24;
                    int dt = (int)(d << (24 - 8 * t)) >> 24;
                    int et = dt ? (abs(bt - dt) - 1) : abs(bt);
                    e |= ((unsigned)et & 0xFFu) << (8 * t);
                }
            }
            wo[2 * q]     = __byte_perm(b, e, 0x5140);   // (b0,e0,b1,e1)
            wo[2 * q + 1] = __byte_perm(b, e, 0x7362);   // (b2,e2,b3,e3)
        }
        int4* dst = (int4*)((char*)s_be + tid * 32);
        dst[0] = make_int4((int)wo[0], (int)wo[1], (int)wo[2], (int)wo[3]);
        dst[1] = make_int4((int)wo[4], (int)wo[5], (int)wo[6], (int)wo[7]);
    }
    const int cj = g_cnt[j];
    const int njg = ((cj + 3) & ~3) >> 1;
    for (int t = tid; t < njg; t += 256) jl[t] = g_list2[(size_t)j * CAPG + t];
    __syncthreads();

    int aS = 0, aE = 0;
    for (int kk = wid; kk < cj; kk += 8) {
        uint2 w = jl[kk >> 1];
        int hi = kk & 1;
        int k = hi ? (int)(w.x >> 16) : (int)(w.x & 0xFFFFu);
        int bkj = hi ? ((int)(w.y << 8) >> 24) : ((int)(w.y << 24) >> 24);
        int ekj = hi ? ((int)w.y >> 24)        : ((int)(w.y << 16) >> 24);
        const uint4* lk = (const uint4*)(g_list2 + (size_t)k * CAPG);
        int ck4 = (__ldg(&g_cnt[k]) + 3) >> 2;
        int sk = 0, ek = 0;
        for (int t = lane; t < ck4; t += 32) {
            uint4 w4 = __ldg(&lk[t]);
            {
                int i0 = (int)(w4.x & 0xFFFFu), i1 = (int)(w4.x >> 16);
                unsigned v0 = *(const unsigned short*)&s_be[i0];
                unsigned v1 = *(const unsigned short*)&s_be[i1];
                unsigned be2 = __byte_perm(v0, v1, 0x5410);
                sk = __dp4a((int)(w4.y & 0x00FF00FFu), (int)be2, sk);
                ek = __dp4a((int)(w4.y & 0xFF00FF00u), (int)be2, ek);
            }
            {
                int i0 = (int)(w4.z & 0xFFFFu), i1 = (int)(w4.z >> 16);
                unsigned v0 = *(const unsigned short*)&s_be[i0];
                unsigned v1 = *(const unsigned short*)&s_be[i1];
                unsigned be2 = __byte_perm(v0, v1, 0x5410);
                sk = __dp4a((int)(w4.w & 0x00FF00FFu), (int)be2, sk);
                ek = __dp4a((int)(w4.w & 0xFF00FF00u), (int)be2, ek);
            }
        }
        aS += bkj * sk;
        aE += ekj * ek;
    }
    #pragma unroll
    for (int o = 16; o > 0; o >>= 1) {
        aS += __shfl_down_sync(0xFFFFFFFFu, aS, o);
        aE += __shfl_down_sync(0xFFFFFFFFu, aE, o);
    }
    if (lane == 0) { redS[wid] = aS; redE[wid] = aE; }
    __syncthreads();
    if (tid == 0) {
        long long s = 0, t = 0;
        #pragma unroll
        for (int w = 0; w < 8; w++) { s += redS[w]; t += redE[w]; }
        atomicAdd(&g_triS, (unsigned long long)s);
        atomicAdd(&g_triE, (unsigned long long)t);
    }
}

// tr(A^3)  = tr(B^3) - 3*T1 + 3*S*T2 - S^3
// tr(|A|^3)= tr(E^3) + 3*TA + 3*|D|*TB + |D|^3
__global__ void k_finish(float* __restrict__ out, int out_size) {
    long long triS = (long long)g_triS, triE = (long long)g_triE;
    long long T1 = (long long)g_T1, T2 = (long long)g_T2, Sv = (long long)g_S;
    long long TA = (long long)g_TA, TB = (long long)g_TB;
    long long nD = g_nD;
    long long tr3  = triS - 3 * T1 + 3 * Sv * T2 - Sv * Sv * Sv;
    long long tr3a = triE + 3 * TA + 3 * nD * TB + nD * nD * nD;
    out[out_size - 1] = (float)(0.5 * (1.0 + (double)tr3 / (double)tr3a));
}

// ---------------- launch ----------------
extern "C" void kernel_launch(void* const* d_in, const int* in_sizes, int n_in,
                              void* d_out, int out_size) {
    const float* ori = (const float*)d_in[0];
    const float* cp  = (const float*)d_in[1];
    const float* u   = (const float*)d_in[2];
    float* out = (float*)d_out;

    k_fuse<<<dim3(128, 128), dim3(8, 32)>>>(ori, cp, u, out);
    k_lists<<<NN, 256>>>();
    k_tri<<<NN, 256>>>();
    k_finish<<<1, 1>>>(out, out_size);
}